// round 10
// baseline (speedup 1.0000x reference)
#include <cuda_runtime.h>
#include <cuda_fp16.h>

// 1M tasks x 40-step rollout -> scalar. R10 = R9's pipe balance without R9's
// scheduling mistake.
//   - k=2 tanh (h2,h3) on FMA/ALU-pipe Pade(5,4); 6 on MUFU.
//     Per warp-iter: MUFU ~192 cyc, FMA ~212 cyc (balanced).
//   - 4 tasks/thread as 2 independent half2 chains (ILP).
//   - Direct-indexed 1024 blocks (measured-best scheduling; persistent grid
//     regressed 25% in R9 from coarse-quantum imbalance).

typedef unsigned int u32;

#define DT      0.05f
#define TPB     256
#define MAX_BLOCKS 4096

__device__ float g_part_err[MAX_BLOCKS];
__device__ float g_part_nor[MAX_BLOCKS];
__device__ unsigned int g_count = 0;

__device__ __forceinline__ __half2 tanh2(__half2 x) {
    u32 xu = *reinterpret_cast<u32*>(&x);
    u32 r;
    asm("tanh.approx.f16x2 %0, %1;" : "=r"(r) : "r"(xu));
    return *reinterpret_cast<__half2*>(&r);
}

// Division-free Pade(5,4) tanh in half2 (FMA/ALU pipes only; no MUFU).
__device__ __forceinline__ __half2 tanh2_pade(__half2 x) {
    const __half2 CLP  = __float2half2_rn(3.6f);
    const __half2 NCLP = __float2half2_rn(-3.6f);
    const __half2 ONE  = __float2half2_rn(1.0f);
    const __half2 TWO  = __float2half2_rn(2.0f);
    const __half2 A1   = __float2half2_rn(1.0f / 945.0f);
    const __half2 A2   = __float2half2_rn(1.0f / 9.0f);
    const __half2 B1   = __float2half2_rn(15.0f / 945.0f);
    const __half2 B2   = __float2half2_rn(420.0f / 945.0f);

    x = __hmin2(__hmax2(x, NCLP), CLP);
    __half2 t   = __hmul2(x, x);
    __half2 num = __hfma2(t, __hfma2(t, A1, A2), ONE);
    __half2 den = __hfma2(t, __hfma2(t, B1, B2), ONE);

    u32 db = *reinterpret_cast<u32*>(&den);
    u32 sb = 0x78007800u - db;                 // rcp seed, no cross-half borrow
    __half2 r = *reinterpret_cast<__half2*>(&sb);
    __half2 nd = __hneg2(den);
    r = __hmul2(r, __hfma2(nd, r, TWO));       // Newton 1
    r = __hmul2(r, __hfma2(nd, r, TWO));       // Newton 2 -> ~fp16 ulp
    return __hmul2(__hmul2(x, num), r);
}

__global__ void __launch_bounds__(TPB, 3)
rollout_kernel(const float* __restrict__ omega,
               const float* __restrict__ Wh1, const float* __restrict__ bh1,
               const float* __restrict__ Wh2, const float* __restrict__ bh2,
               const float* __restrict__ Wr1, const float* __restrict__ br1,
               const float* __restrict__ Wr2, const float* __restrict__ br2,
               const float* __restrict__ alpha,
               float* __restrict__ out,
               int N, int nblocks)
{
    const int gi = blockIdx.x * TPB + threadIdx.x;   // quad index
    const int base = 4 * gi;

    // ---- broadcast weights (half2 in-loop copies) ----
    __half2 Wc2h[4], Wc3h[4], W2h[4], BH2h;
    __half2 Wrh[9], Brh[3], Woh[3], Boh;
    float wc0[4], wc1[4], vb1[4];
#pragma unroll
    for (int k = 0; k < 4; k++) {
        wc0[k]  = __ldg(Wh1 + 4 * k + 0);
        wc1[k]  = __ldg(Wh1 + 4 * k + 1);
        Wc2h[k] = __float2half2_rn(__ldg(Wh1 + 4 * k + 2));
        Wc3h[k] = __float2half2_rn(__ldg(Wh1 + 4 * k + 3));
        vb1[k]  = __ldg(bh1 + k);
        W2h[k]  = __float2half2_rn(__ldg(Wh2 + k));
    }
    BH2h = __float2half2_rn(__ldg(bh2));
#pragma unroll
    for (int k = 0; k < 9; k++) Wrh[k] = __float2half2_rn(__ldg(Wr1 + k));
#pragma unroll
    for (int k = 0; k < 3; k++) {
        Brh[k] = __float2half2_rn(__ldg(br1 + k));
        Woh[k] = __float2half2_rn(__ldg(Wr2 + k));
    }
    Boh = __float2half2_rn(__ldg(br2));
    const __half2 PT1h = __float2half2_rn(0.1f);
    const __half2 THRh = __float2half2_rn(0.01f);
    const __half2 TENh = __float2half2_rn(10.0f);
    const __half2 DTh  = __float2half2_rn(DT);
    const __half2 Z2   = __float2half2_rn(0.0f);

    // ---- per-task targets (4 tasks = 2 chains) ----
    float t0[4], t1[4], m[4];
#pragma unroll
    for (int k = 0; k < 4; k++) {
        t0[k] = 0.0f; t1[k] = 0.0f;
        m[k] = ((base + k) < N) ? 1.0f : 0.0f;
    }
    if ((base + 3) < N && (N & 3) == 0) {
        float4 o0 = __ldg(reinterpret_cast<const float4*>(omega + base));
        t0[0] = o0.x; t0[1] = o0.y; t0[2] = o0.z; t0[3] = o0.w;
        float4 o1 = __ldg(reinterpret_cast<const float4*>(omega + N + base));
        t1[0] = o1.x; t1[1] = o1.y; t1[2] = o1.z; t1[3] = o1.w;
    } else {
#pragma unroll
        for (int k = 0; k < 4; k++) {
            if (m[k] != 0.0f) {
                t0[k] = __ldg(omega + base + k);
                t1[k] = __ldg(omega + N + base + k);
            }
        }
    }

    // per-chain constants (fp32 math, stored half2)
    __half2 CH[2][4], CZT[2], T0h[2], T1h[2];
#pragma unroll
    for (int p = 0; p < 2; p++) {
#pragma unroll
        for (int k = 0; k < 4; k++)
            CH[p][k] = __floats2half2_rn(
                fmaf(wc0[k], t0[2*p],   fmaf(wc1[k], t1[2*p],   vb1[k])),
                fmaf(wc0[k], t0[2*p+1], fmaf(wc1[k], t1[2*p+1], vb1[k])));
        CZT[p] = __floats2half2_rn(fmaf(0.1f, t1[2*p],   t0[2*p]),
                                   fmaf(0.1f, t1[2*p+1], t0[2*p+1]));
        T0h[p] = __floats2half2_rn(t0[2*p], t0[2*p+1]);
        T1h[p] = __floats2half2_rn(t1[2*p], t1[2*p+1]);
    }

    __half2 S0h[2] = {Z2, Z2}, S1h[2] = {Z2, Z2};
    __half2 ERRh[2] = {Z2, Z2}, NORh[2] = {Z2, Z2}, EFFh[2] = {Z2, Z2};
    float errT = 0.0f, norT = 0.0f;

#pragma unroll 1
    for (int ph = 0; ph < 5; ph++) {       // 5 phases x 8 steps = 40
#pragma unroll
        for (int st = 0; st < 8; st++) {
#pragma unroll
            for (int p = 0; p < 2; p++) {
                // err term: 10 e0^2 + e1^2
                __half2 e0 = __hsub2(T0h[p], S0h[p]);
                __half2 e1 = __hsub2(T1h[p], S1h[p]);
                __half2 q0 = __hmul2(e0, e0);
                ERRh[p] = __hfma2(TENh, q0, __hfma2(e1, e1, ERRh[p]));

                // human MLP; h2,h3 on FMA-pipe Pade, h0,h1,z on MUFU
                __half2 H0 = tanh2(__hfma2(Wc2h[0], S0h[p], __hfma2(Wc3h[0], S1h[p], CH[p][0])));
                __half2 H1 = tanh2(__hfma2(Wc2h[1], S0h[p], __hfma2(Wc3h[1], S1h[p], CH[p][1])));
                __half2 H2 = tanh2_pade(__hfma2(Wc2h[2], S0h[p], __hfma2(Wc3h[2], S1h[p], CH[p][2])));
                __half2 H3 = tanh2_pade(__hfma2(Wc2h[3], S0h[p], __hfma2(Wc3h[3], S1h[p], CH[p][3])));
                __half2 Z  = tanh2(__hfma2(W2h[0], H0, __hfma2(W2h[1], H1,
                                   __hfma2(W2h[2], H2, __hfma2(W2h[3], H3, BH2h)))));

                // robot MLP: xr = [s0, s1, z]
                __half2 R0 = tanh2(__hfma2(Wrh[0], S0h[p], __hfma2(Wrh[1], S1h[p], __hfma2(Wrh[2], Z, Brh[0]))));
                __half2 R1 = tanh2(__hfma2(Wrh[3], S0h[p], __hfma2(Wrh[4], S1h[p], __hfma2(Wrh[5], Z, Brh[1]))));
                __half2 R2 = tanh2(__hfma2(Wrh[6], S0h[p], __hfma2(Wrh[7], S1h[p], __hfma2(Wrh[8], Z, Brh[2]))));
                __half2 Ah = __hfma2(Woh[0], R0, __hfma2(Woh[1], R1, __hfma2(Woh[2], R2, Boh)));

                // divergence: d = czt - (s0 + 0.1 s1) - z
                __half2 w = __hfma2(PT1h, S1h[p], S0h[p]);
                __half2 d = __hsub2(__hsub2(CZT[p], w), Z);
                NORh[p] = __hfma2(d, d, NORh[p]);

                // effort: |z| > 0.01 (exact small-int fp16 counting)
                EFFh[p] = __hadd2(EFFh[p], __hgt2(__habs2(Z), THRh));

                // dynamics
                __half2 nS0 = __hfma2(DTh, S1h[p], S0h[p]);
                S1h[p] = __hfma2(DTh, Ah, S1h[p]);
                S0h[p] = nS0;
            }
        }
        // flush partial sums to fp32 (mask-folded)
#pragma unroll
        for (int p = 0; p < 2; p++) {
            float2 ef = __half22float2(ERRh[p]);
            float2 nf = __half22float2(NORh[p]);
            errT = fmaf(m[2*p], ef.x, fmaf(m[2*p+1], ef.y, errT));
            norT = fmaf(m[2*p], nf.x, fmaf(m[2*p+1], nf.y, norT));
            ERRh[p] = Z2; NORh[p] = Z2;
        }
    }

    // final error term on s_40 + eff, mask-folded
    float sumA = errT, sumB = norT;
#pragma unroll
    for (int p = 0; p < 2; p++) {
        float2 s0f = __half22float2(S0h[p]);
        float2 s1f = __half22float2(S1h[p]);
        float2 ev  = __half22float2(EFFh[p]);
        float e0 = t0[2*p] - s0f.x, e1 = t1[2*p] - s1f.x;
        float fin = fmaf(10.0f * e0, e0, e1 * e1);
        sumA = fmaf(m[2*p], fin + ev.x, sumA);
        e0 = t0[2*p+1] - s0f.y; e1 = t1[2*p+1] - s1f.y;
        fin = fmaf(10.0f * e0, e0, e1 * e1);
        sumA = fmaf(m[2*p+1], fin + ev.y, sumA);
    }

    // ---- block reduce ----
#pragma unroll
    for (int off = 16; off > 0; off >>= 1) {
        sumA += __shfl_down_sync(0xFFFFFFFFu, sumA, off);
        sumB += __shfl_down_sync(0xFFFFFFFFu, sumB, off);
    }
    __shared__ float shA[TPB / 32];
    __shared__ float shB[TPB / 32];
    const int lane = threadIdx.x & 31;
    const int wid  = threadIdx.x >> 5;
    if (lane == 0) { shA[wid] = sumA; shB[wid] = sumB; }
    __syncthreads();
    if (wid == 0) {
        sumA = (lane < TPB / 32) ? shA[lane] : 0.0f;
        sumB = (lane < TPB / 32) ? shB[lane] : 0.0f;
#pragma unroll
        for (int off = (TPB / 64); off > 0; off >>= 1) {
            sumA += __shfl_down_sync(0xFFFFFFFFu, sumA, off);
            sumB += __shfl_down_sync(0xFFFFFFFFu, sumB, off);
        }
        if (lane == 0) {
            g_part_err[blockIdx.x] = sumA;
            g_part_nor[blockIdx.x] = sumB;
        }
    }

    // ---- last-block deterministic final reduction ----
    __shared__ unsigned int s_is_last;
    __threadfence();
    if (threadIdx.x == 0) {
        unsigned int old = atomicAdd(&g_count, 1u);
        s_is_last = (old == (unsigned int)(nblocks - 1)) ? 1u : 0u;
    }
    __syncthreads();

    if (s_is_last) {
        __shared__ double dA[TPB];
        __shared__ double dB[TPB];
        double a = 0.0, b = 0.0;
        for (int k = threadIdx.x; k < nblocks; k += TPB) {
            a += (double)__ldcg(&g_part_err[k]);
            b += (double)__ldcg(&g_part_nor[k]);
        }
        dA[threadIdx.x] = a;
        dB[threadIdx.x] = b;
        __syncthreads();
#pragma unroll
        for (int s = TPB / 2; s > 0; s >>= 1) {
            if (threadIdx.x < s) {
                dA[threadIdx.x] += dA[threadIdx.x + s];
                dB[threadIdx.x] += dB[threadIdx.x + s];
            }
            __syncthreads();
        }
        if (threadIdx.x == 0) {
            double invN = 1.0 / (double)N;
            out[0] = (float)(dA[0] * invN + (double)__ldg(alpha) * (dB[0] * invN));
            g_count = 0;   // reset for next graph replay
        }
    }
}

extern "C" void kernel_launch(void* const* d_in, const int* in_sizes, int n_in,
                              void* d_out, int out_size)
{
    // metadata order: omega, Wh1, bh1, Wh2, bh2, Wr1, br1, Wr2, br2, alpha, n_tasks
    const float* omega = (const float*)d_in[0];
    const float* Wh1   = (const float*)d_in[1];
    const float* bh1   = (const float*)d_in[2];
    const float* Wh2   = (const float*)d_in[3];
    const float* bh2   = (const float*)d_in[4];
    const float* Wr1   = (const float*)d_in[5];
    const float* br1   = (const float*)d_in[6];
    const float* Wr2   = (const float*)d_in[7];
    const float* br2   = (const float*)d_in[8];
    const float* alpha = (const float*)d_in[9];

    const int N = in_sizes[0] / 2;                 // omega is [2, N]
    const int nquads = (N + 3) / 4;                // 4 tasks per thread
    int nblocks = (nquads + TPB - 1) / TPB;        // N=1M -> 1024
    if (nblocks > MAX_BLOCKS) nblocks = MAX_BLOCKS;

    rollout_kernel<<<nblocks, TPB>>>(omega, Wh1, bh1, Wh2, bh2,
                                     Wr1, br1, Wr2, br2, alpha,
                                     (float*)d_out, N, nblocks);
}

// round 11
// speedup vs baseline: 1.7671x; 1.7671x over previous
#include <cuda_runtime.h>
#include <cuda_fp16.h>

// 1M tasks x 40-step rollout -> scalar. R11: minimize issued instructions.
// Cross-round evidence (R8->R9/R10): duration tracks total issued instrs;
// MUFU is NOT the binder (tanh.approx.f16x2 ~1 MUFU op, pipe ~45% busy).
// So: all 8 tanh back on MUFU (drop Pade, -26 instr/warp-iter), split err
// accumulators (save hmul), reuse e0/e1 for divergence (save 1 op).
// Keep R8's measured-best config: 4 tasks/thread as 2 half2 chains,
// TPB=256, direct-indexed 1024 blocks, 3 CTAs/SM.

typedef unsigned int u32;

#define DT      0.05f
#define TPB     256
#define MAX_BLOCKS 4096

__device__ float g_part_err[MAX_BLOCKS];
__device__ float g_part_nor[MAX_BLOCKS];
__device__ unsigned int g_count = 0;

__device__ __forceinline__ __half2 tanh2(__half2 x) {
    u32 xu = *reinterpret_cast<u32*>(&x);
    u32 r;
    asm("tanh.approx.f16x2 %0, %1;" : "=r"(r) : "r"(xu));
    return *reinterpret_cast<__half2*>(&r);
}

__global__ void __launch_bounds__(TPB, 3)
rollout_kernel(const float* __restrict__ omega,
               const float* __restrict__ Wh1, const float* __restrict__ bh1,
               const float* __restrict__ Wh2, const float* __restrict__ bh2,
               const float* __restrict__ Wr1, const float* __restrict__ br1,
               const float* __restrict__ Wr2, const float* __restrict__ br2,
               const float* __restrict__ alpha,
               float* __restrict__ out,
               int N, int nblocks)
{
    const int gi = blockIdx.x * TPB + threadIdx.x;   // quad index
    const int base = 4 * gi;

    // ---- broadcast weights (half2 in-loop copies) ----
    __half2 Wc2h[4], Wc3h[4], W2h[4], BH2h;
    __half2 Wrh[9], Brh[3], Woh[3], Boh;
    float wc0[4], wc1[4], vb1[4];
#pragma unroll
    for (int k = 0; k < 4; k++) {
        wc0[k]  = __ldg(Wh1 + 4 * k + 0);
        wc1[k]  = __ldg(Wh1 + 4 * k + 1);
        Wc2h[k] = __float2half2_rn(__ldg(Wh1 + 4 * k + 2));
        Wc3h[k] = __float2half2_rn(__ldg(Wh1 + 4 * k + 3));
        vb1[k]  = __ldg(bh1 + k);
        W2h[k]  = __float2half2_rn(__ldg(Wh2 + k));
    }
    BH2h = __float2half2_rn(__ldg(bh2));
#pragma unroll
    for (int k = 0; k < 9; k++) Wrh[k] = __float2half2_rn(__ldg(Wr1 + k));
#pragma unroll
    for (int k = 0; k < 3; k++) {
        Brh[k] = __float2half2_rn(__ldg(br1 + k));
        Woh[k] = __float2half2_rn(__ldg(Wr2 + k));
    }
    Boh = __float2half2_rn(__ldg(br2));
    const __half2 PT1h = __float2half2_rn(0.1f);
    const __half2 THRh = __float2half2_rn(0.01f);
    const __half2 DTh  = __float2half2_rn(DT);
    const __half2 Z2   = __float2half2_rn(0.0f);

    // ---- per-task targets (4 tasks = 2 chains) ----
    float t0[4], t1[4], m[4];
#pragma unroll
    for (int k = 0; k < 4; k++) {
        t0[k] = 0.0f; t1[k] = 0.0f;
        m[k] = ((base + k) < N) ? 1.0f : 0.0f;
    }
    if ((base + 3) < N && (N & 3) == 0) {
        float4 o0 = __ldg(reinterpret_cast<const float4*>(omega + base));
        t0[0] = o0.x; t0[1] = o0.y; t0[2] = o0.z; t0[3] = o0.w;
        float4 o1 = __ldg(reinterpret_cast<const float4*>(omega + N + base));
        t1[0] = o1.x; t1[1] = o1.y; t1[2] = o1.z; t1[3] = o1.w;
    } else {
#pragma unroll
        for (int k = 0; k < 4; k++) {
            if (m[k] != 0.0f) {
                t0[k] = __ldg(omega + base + k);
                t1[k] = __ldg(omega + N + base + k);
            }
        }
    }

    // per-chain constants (fp32 math, stored half2)
    __half2 CH[2][4], T0h[2], T1h[2];
#pragma unroll
    for (int p = 0; p < 2; p++) {
#pragma unroll
        for (int k = 0; k < 4; k++)
            CH[p][k] = __floats2half2_rn(
                fmaf(wc0[k], t0[2*p],   fmaf(wc1[k], t1[2*p],   vb1[k])),
                fmaf(wc0[k], t0[2*p+1], fmaf(wc1[k], t1[2*p+1], vb1[k])));
        T0h[p] = __floats2half2_rn(t0[2*p], t0[2*p+1]);
        T1h[p] = __floats2half2_rn(t1[2*p], t1[2*p+1]);
    }

    __half2 S0h[2] = {Z2, Z2}, S1h[2] = {Z2, Z2};
    __half2 ERR0h[2] = {Z2, Z2}, ERR1h[2] = {Z2, Z2};
    __half2 NORh[2] = {Z2, Z2}, EFFh[2] = {Z2, Z2};
    float errT = 0.0f, norT = 0.0f;

#pragma unroll 1
    for (int ph = 0; ph < 5; ph++) {       // 5 phases x 8 steps = 40
#pragma unroll
        for (int st = 0; st < 8; st++) {
#pragma unroll
            for (int p = 0; p < 2; p++) {
                // error components (reused for err accum AND divergence)
                __half2 e0 = __hsub2(T0h[p], S0h[p]);
                __half2 e1 = __hsub2(T1h[p], S1h[p]);
                ERR0h[p] = __hfma2(e0, e0, ERR0h[p]);   // x10 applied at flush
                ERR1h[p] = __hfma2(e1, e1, ERR1h[p]);

                // human MLP (s_star part hoisted into CH); all tanh on MUFU
                __half2 H0 = tanh2(__hfma2(Wc2h[0], S0h[p], __hfma2(Wc3h[0], S1h[p], CH[p][0])));
                __half2 H1 = tanh2(__hfma2(Wc2h[1], S0h[p], __hfma2(Wc3h[1], S1h[p], CH[p][1])));
                __half2 H2 = tanh2(__hfma2(Wc2h[2], S0h[p], __hfma2(Wc3h[2], S1h[p], CH[p][2])));
                __half2 H3 = tanh2(__hfma2(Wc2h[3], S0h[p], __hfma2(Wc3h[3], S1h[p], CH[p][3])));
                __half2 Z  = tanh2(__hfma2(W2h[0], H0, __hfma2(W2h[1], H1,
                                   __hfma2(W2h[2], H2, __hfma2(W2h[3], H3, BH2h)))));

                // robot MLP: xr = [s0, s1, z]
                __half2 R0 = tanh2(__hfma2(Wrh[0], S0h[p], __hfma2(Wrh[1], S1h[p], __hfma2(Wrh[2], Z, Brh[0]))));
                __half2 R1 = tanh2(__hfma2(Wrh[3], S0h[p], __hfma2(Wrh[4], S1h[p], __hfma2(Wrh[5], Z, Brh[1]))));
                __half2 R2 = tanh2(__hfma2(Wrh[6], S0h[p], __hfma2(Wrh[7], S1h[p], __hfma2(Wrh[8], Z, Brh[2]))));
                __half2 Ah = __hfma2(Woh[0], R0, __hfma2(Woh[1], R1, __hfma2(Woh[2], R2, Boh)));

                // divergence: d = zt - z = (e0 - z) + 0.1*e1 (reuses e0,e1)
                __half2 d = __hfma2(PT1h, e1, __hsub2(e0, Z));
                NORh[p] = __hfma2(d, d, NORh[p]);

                // effort: |z| > 0.01 (exact small-int fp16 counting)
                EFFh[p] = __hadd2(EFFh[p], __hgt2(__habs2(Z), THRh));

                // dynamics
                __half2 nS0 = __hfma2(DTh, S1h[p], S0h[p]);
                S1h[p] = __hfma2(DTh, Ah, S1h[p]);
                S0h[p] = nS0;
            }
        }
        // flush partial sums to fp32 (mask-folded; x10 weight applied here)
#pragma unroll
        for (int p = 0; p < 2; p++) {
            float2 e0f = __half22float2(ERR0h[p]);
            float2 e1f = __half22float2(ERR1h[p]);
            float2 nf  = __half22float2(NORh[p]);
            errT = fmaf(m[2*p],   fmaf(10.0f, e0f.x, e1f.x),
                   fmaf(m[2*p+1], fmaf(10.0f, e0f.y, e1f.y), errT));
            norT = fmaf(m[2*p], nf.x, fmaf(m[2*p+1], nf.y, norT));
            ERR0h[p] = Z2; ERR1h[p] = Z2; NORh[p] = Z2;
        }
    }

    // final error term on s_40 + eff, mask-folded
    float sumA = errT, sumB = norT;
#pragma unroll
    for (int p = 0; p < 2; p++) {
        float2 s0f = __half22float2(S0h[p]);
        float2 s1f = __half22float2(S1h[p]);
        float2 ev  = __half22float2(EFFh[p]);
        float e0 = t0[2*p] - s0f.x, e1 = t1[2*p] - s1f.x;
        float fin = fmaf(10.0f * e0, e0, e1 * e1);
        sumA = fmaf(m[2*p], fin + ev.x, sumA);
        e0 = t0[2*p+1] - s0f.y; e1 = t1[2*p+1] - s1f.y;
        fin = fmaf(10.0f * e0, e0, e1 * e1);
        sumA = fmaf(m[2*p+1], fin + ev.y, sumA);
    }

    // ---- block reduce ----
#pragma unroll
    for (int off = 16; off > 0; off >>= 1) {
        sumA += __shfl_down_sync(0xFFFFFFFFu, sumA, off);
        sumB += __shfl_down_sync(0xFFFFFFFFu, sumB, off);
    }
    __shared__ float shA[TPB / 32];
    __shared__ float shB[TPB / 32];
    const int lane = threadIdx.x & 31;
    const int wid  = threadIdx.x >> 5;
    if (lane == 0) { shA[wid] = sumA; shB[wid] = sumB; }
    __syncthreads();
    if (wid == 0) {
        sumA = (lane < TPB / 32) ? shA[lane] : 0.0f;
        sumB = (lane < TPB / 32) ? shB[lane] : 0.0f;
#pragma unroll
        for (int off = (TPB / 64); off > 0; off >>= 1) {
            sumA += __shfl_down_sync(0xFFFFFFFFu, sumA, off);
            sumB += __shfl_down_sync(0xFFFFFFFFu, sumB, off);
        }
        if (lane == 0) {
            g_part_err[blockIdx.x] = sumA;
            g_part_nor[blockIdx.x] = sumB;
        }
    }

    // ---- last-block deterministic final reduction ----
    __shared__ unsigned int s_is_last;
    __threadfence();
    if (threadIdx.x == 0) {
        unsigned int old = atomicAdd(&g_count, 1u);
        s_is_last = (old == (unsigned int)(nblocks - 1)) ? 1u : 0u;
    }
    __syncthreads();

    if (s_is_last) {
        __shared__ double dA[TPB];
        __shared__ double dB[TPB];
        double a = 0.0, b = 0.0;
        for (int k = threadIdx.x; k < nblocks; k += TPB) {
            a += (double)__ldcg(&g_part_err[k]);
            b += (double)__ldcg(&g_part_nor[k]);
        }
        dA[threadIdx.x] = a;
        dB[threadIdx.x] = b;
        __syncthreads();
#pragma unroll
        for (int s = TPB / 2; s > 0; s >>= 1) {
            if (threadIdx.x < s) {
                dA[threadIdx.x] += dA[threadIdx.x + s];
                dB[threadIdx.x] += dB[threadIdx.x + s];
            }
            __syncthreads();
        }
        if (threadIdx.x == 0) {
            double invN = 1.0 / (double)N;
            out[0] = (float)(dA[0] * invN + (double)__ldg(alpha) * (dB[0] * invN));
            g_count = 0;   // reset for next graph replay
        }
    }
}

extern "C" void kernel_launch(void* const* d_in, const int* in_sizes, int n_in,
                              void* d_out, int out_size)
{
    // metadata order: omega, Wh1, bh1, Wh2, bh2, Wr1, br1, Wr2, br2, alpha, n_tasks
    const float* omega = (const float*)d_in[0];
    const float* Wh1   = (const float*)d_in[1];
    const float* bh1   = (const float*)d_in[2];
    const float* Wh2   = (const float*)d_in[3];
    const float* bh2   = (const float*)d_in[4];
    const float* Wr1   = (const float*)d_in[5];
    const float* br1   = (const float*)d_in[6];
    const float* Wr2   = (const float*)d_in[7];
    const float* br2   = (const float*)d_in[8];
    const float* alpha = (const float*)d_in[9];

    const int N = in_sizes[0] / 2;                 // omega is [2, N]
    const int nquads = (N + 3) / 4;                // 4 tasks per thread
    int nblocks = (nquads + TPB - 1) / TPB;        // N=1M -> 1024
    if (nblocks > MAX_BLOCKS) nblocks = MAX_BLOCKS;

    rollout_kernel<<<nblocks, TPB>>>(omega, Wh1, bh1, Wh2, bh2,
                                     Wr1, br1, Wr2, br2, alpha,
                                     (float*)d_out, N, nblocks);
}